// round 16
// baseline (speedup 1.0000x reference)
#include <cuda_runtime.h>
#include <cuda_bf16.h>
#include <cstddef>

#define E_TOT 512
#define Dd    64
#define Hh    256
#define Nn    16
#define Aa    8
#define Tt    128
#define HO    (Nn + Aa * Nn)   // 144 head outputs
#define USTR  20               // U row stride: 80B = 5x16B, float4-aligned
#define H1STR 260              // h1 smem row stride: 1040B = 65x16B

#define SF2   0.01f
#define SN2   0.01f
#define NEG_HALF_INV_L2 (-50.0f)   // -0.5 / 0.1^2

// scratch (no allocation allowed -> device globals)
__device__ float g_h2[E_TOT * Hh];     // layer-2 activations
__device__ float g_head[E_TOT * HO];   // [times(16) | anchors(128)] per e

// ---------------------------------------------------------------------------
// Fused layer1+layer2 kernel. Grid (E/16, 256/32) = 256 blocks, 256 threads.
//   Phase A: block computes its FULL 16x256 h1 tile in smem (8 subtiles of
//            32 cols, proven micro-kernel pattern; W1 re-read is L2-hot).
//   Phase B: layer-2 k-loop reads A straight from h1 smem (no staging, no
//            global h1 round-trip), W2 tiles double-buffered via registers.
// ---------------------------------------------------------------------------
__global__ __launch_bounds__(256)
void fused_l12_kernel(const float* __restrict__ x,
                      const float* __restrict__ W1, const float* __restrict__ b1,
                      const float* __restrict__ W2, const float* __restrict__ b2)
{
    __shared__ __align__(16) float xs [16][68];      // x tile   [row][k]
    __shared__ __align__(16) float W1s[32][68];      // W1 sub   [col][k]
    __shared__ __align__(16) float h1s[16][H1STR];   // h1 tile  [row][col]
    __shared__ __align__(16) float Bsh[32][68];      // W2 tile  [col][k]

    const int tid  = threadIdx.x;
    const int c    = tid & 31;           // col within 32-subtile
    const int rg   = tid >> 5;           // row group 0..7 (2 rows each)
    const int row0 = blockIdx.x * 16;
    const int col0 = blockIdx.y * 32;    // layer-2 output cols

    // stage x tile: 16 rows x 16 float4 = 256, one per thread
    {
        int r = tid >> 4, kq = (tid & 15) << 2;
        *(float4*)&xs[r][kq] = *(const float4*)&x[(row0 + r) * Dd + kq];
    }

    // ---- Phase A: h1 tile, 8 subtiles of 32 cols ----
    for (int ct = 0; ct < 8; ct++) {
        __syncthreads();                 // protect W1s from previous subtile
        #pragma unroll
        for (int u = 0; u < 2; u++) {    // 32 cols x 16 f4 = 512 loads
            int i  = tid + u * 256;
            int cc = i >> 4, kq = (i & 15) << 2;
            *(float4*)&W1s[cc][kq] = *(const float4*)&W1[(ct * 32 + cc) * Dd + kq];
        }
        __syncthreads();

        float a0[2] = {0.f, 0.f}, a1[2] = {0.f, 0.f},
              a2[2] = {0.f, 0.f}, a3[2] = {0.f, 0.f};
        #pragma unroll
        for (int kk = 0; kk < Dd; kk += 4) {
            float4 b4 = *(const float4*)&W1s[c][kk];       // conflict-free
            #pragma unroll
            for (int r = 0; r < 2; r++) {
                float4 a4 = *(const float4*)&xs[rg * 2 + r][kk];  // broadcast
                a0[r] += a4.x * b4.x;
                a1[r] += a4.y * b4.y;
                a2[r] += a4.z * b4.z;
                a3[r] += a4.w * b4.w;
            }
        }
        float bv = b1[ct * 32 + c];
        #pragma unroll
        for (int r = 0; r < 2; r++)
            h1s[rg * 2 + r][ct * 32 + c] =
                tanhf((a0[r] + a1[r]) + (a2[r] + a3[r]) + bv);
    }
    __syncthreads();

    // ---- Phase B: layer 2 (k=256), A from h1s, W2 double-buffered ----
    float acc[2][4];
    #pragma unroll
    for (int r = 0; r < 2; r++)
        #pragma unroll
        for (int q = 0; q < 4; q++) acc[r][q] = 0.0f;

    float4 pw[2];
    #pragma unroll
    for (int u = 0; u < 2; u++) {        // prefetch W2 tile 0
        int i  = tid + u * 256;
        int cc = i >> 4, kq = (i & 15) << 2;
        pw[u] = *(const float4*)&W2[(col0 + cc) * Hh + kq];
    }

    for (int k0 = 0; k0 < Hh; k0 += 64) {
        #pragma unroll
        for (int u = 0; u < 2; u++) {
            int i  = tid + u * 256;
            int cc = i >> 4, kq = (i & 15) << 2;
            *(float4*)&Bsh[cc][kq] = pw[u];
        }
        __syncthreads();

        if (k0 + 64 < Hh) {
            int kn = k0 + 64;
            #pragma unroll
            for (int u = 0; u < 2; u++) {
                int i  = tid + u * 256;
                int cc = i >> 4, kq = (i & 15) << 2;
                pw[u] = *(const float4*)&W2[(col0 + cc) * Hh + kn + kq];
            }
        }

        #pragma unroll
        for (int kk = 0; kk < 64; kk += 4) {
            float4 b4 = *(const float4*)&Bsh[c][kk];
            #pragma unroll
            for (int r = 0; r < 2; r++) {
                float4 a4 = *(const float4*)&h1s[rg * 2 + r][k0 + kk];  // broadcast
                acc[r][0] += a4.x * b4.x;
                acc[r][1] += a4.y * b4.y;
                acc[r][2] += a4.z * b4.z;
                acc[r][3] += a4.w * b4.w;
            }
        }
        __syncthreads();
    }

    float bv = b2[col0 + c];
    #pragma unroll
    for (int r = 0; r < 2; r++) {
        int row = row0 + rg * 2 + r;
        g_h2[row * Hh + col0 + c] =
            tanhf((acc[r][0] + acc[r][1]) + (acc[r][2] + acc[r][3]) + bv);
    }
}

// ---------------------------------------------------------------------------
// Heads GEMM (R15 exact): BN=16, SPLITW, 288 blocks, prefetch double-buffer.
// ---------------------------------------------------------------------------
__global__ __launch_bounds__(256)
void heads_kernel(const float* __restrict__ A,
                  const float* __restrict__ Wt, const float* __restrict__ Wa,
                  const float* __restrict__ bt, const float* __restrict__ ba,
                  float* __restrict__ C)
{
    constexpr int BM = 16, BN = 16;
    __shared__ __align__(16) float Ash[BM][68];
    __shared__ __align__(16) float Bsh[BN][68];

    const int tid  = threadIdx.x;
    const int c    = tid % BN;
    const int rg   = tid / BN;
    const int row0 = blockIdx.x * BM;
    const int col0 = blockIdx.y * BN;

    float acc[4] = {0.f, 0.f, 0.f, 0.f};

    float4 pa, pw;
    {
        int r = tid >> 4, kq = (tid & 15) << 2;
        pa = *(const float4*)&A[(row0 + r) * Hh + kq];
        int cg = col0 + r;
        const float* src = (cg < Nn) ? &Wt[cg * Hh + kq] : &Wa[(cg - Nn) * Hh + kq];
        pw = *(const float4*)src;
    }

    for (int k0 = 0; k0 < Hh; k0 += 64) {
        {
            int r = tid >> 4, kq = (tid & 15) << 2;
            *(float4*)&Ash[r][kq] = pa;
            *(float4*)&Bsh[r][kq] = pw;
        }
        __syncthreads();

        if (k0 + 64 < Hh) {
            int kn = k0 + 64;
            int r = tid >> 4, kq = (tid & 15) << 2;
            pa = *(const float4*)&A[(row0 + r) * Hh + kn + kq];
            int cg = col0 + r;
            const float* src = (cg < Nn) ? &Wt[cg * Hh + kn + kq]
                                         : &Wa[(cg - Nn) * Hh + kn + kq];
            pw = *(const float4*)src;
        }

        #pragma unroll
        for (int kk = 0; kk < 64; kk += 4) {
            float4 b4 = *(const float4*)&Bsh[c][kk];
            float4 a4 = *(const float4*)&Ash[rg][kk];
            acc[0] += a4.x * b4.x;
            acc[1] += a4.y * b4.y;
            acc[2] += a4.z * b4.z;
            acc[3] += a4.w * b4.w;
        }
        __syncthreads();
    }

    int row = row0 + rg;
    int col = col0 + c;
    float bv = (col < Nn) ? bt[col] : ba[col - Nn];
    C[row * HO + col] = (acc[0] + acc[1]) + (acc[2] + acc[3]) + bv;
}

// ---------------------------------------------------------------------------
// GP per environment e. 512 blocks, 256 threads.  (R15 body, byte-frozen.)
// ---------------------------------------------------------------------------
__global__ __launch_bounds__(256)
void gp_kernel(const float* __restrict__ tq_g,
               float* __restrict__ out_mu,
               float* __restrict__ out_cov)
{
    __shared__ float tq[Tt];
    __shared__ float kssd[Tt];                        // Kss[i][j] == kssd[|i-j|]
    __shared__ float tt[Nn];
    __shared__ float ys[Aa][Nn];
    __shared__ float Aug[Nn][2 * Nn + 1];             // [K | I] -> [I | K^-1]
    __shared__ float colk[Nn];
    __shared__ __align__(16) float St[Nn][Tt + 4];    // Ks^T, pad 132 (16B mult)
    __shared__ __align__(16) float U[Tt][USTR];       // U = Ks K^-1, stride 20

    const int e   = blockIdx.x;
    const int tid = threadIdx.x;

    if (tid < Tt) tq[tid] = tq_g[tid];
    if (tid < Nn) tt[tid] = g_head[e * HO + tid];
    if (tid >= 128 && tid < 128 + Aa * Nn) {
        int q = tid - 128;
        ys[q >> 4][q & 15] = g_head[e * HO + Nn + q];
    }
    __syncthreads();

    if (tid < Tt) {
        float d = tq[tid] - tq[0];
        kssd[tid] = SF2 * __expf(NEG_HALF_INV_L2 * d * d);
    }
    // build [K + sn2 I | I]
    {
        int i = tid >> 4, j = tid & 15;
        float d = tt[i] - tt[j];
        float v = SF2 * __expf(NEG_HALF_INV_L2 * d * d);
        if (i == j) v += SN2;
        Aug[i][j] = v;
        Aug[i][Nn + j] = (i == j) ? 1.0f : 0.0f;
    }
    __syncthreads();

    // Gauss-Jordan (SPD, no pivoting needed, cond(K) <= 17)
    for (int k = 0; k < Nn; k++) {
        float pinv = 1.0f / Aug[k][k];
        __syncthreads();
        if (tid < 32) Aug[k][tid] *= pinv;
        if (tid >= 32 && tid < 48) colk[tid - 32] = Aug[tid - 32][k];
        __syncthreads();
        {
            int idx = tid;
            int i0 = idx >> 5, j0 = idx & 31;
            if (i0 != k) Aug[i0][j0] -= colk[i0] * Aug[k][j0];
            idx += 256;
            int i1 = idx >> 5, j1 = idx & 31;
            if (i1 != k) Aug[i1][j1] -= colk[i1] * Aug[k][j1];
        }
        __syncthreads();
    }

    // Ks transposed: St[n][j] = sf2 * exp(-0.5 (tq[j]-t[n])^2 / l2)
    for (int idx = tid; idx < Tt * Nn; idx += 256) {
        int j = idx >> 4, n = idx & 15;
        float d = tq[j] - tt[n];
        St[n][j] = SF2 * __expf(NEG_HALF_INV_L2 * d * d);
    }
    __syncthreads();

    // U[i][n] = sum_m Ks[i][m] * Kinv[m][n]
    for (int idx = tid; idx < Tt * Nn; idx += 256) {
        int i = idx >> 4, n = idx & 15;
        float s = 0.0f;
        #pragma unroll
        for (int m = 0; m < Nn; m++) s += St[m][i] * Aug[m][Nn + n];
        U[i][n] = s;
    }
    __syncthreads();

    // mu[a][i] = dot16(U[i], y[a])   (U rows are 4 aligned float4s)
    for (int idx = tid; idx < Aa * Tt; idx += 256) {
        int a = idx >> 7, i = idx & 127;
        float4 u0 = *(const float4*)&U[i][0];
        float4 u1 = *(const float4*)&U[i][4];
        float4 u2 = *(const float4*)&U[i][8];
        float4 u3 = *(const float4*)&U[i][12];
        float s = u0.x * ys[a][0]  + u0.y * ys[a][1]  + u0.z * ys[a][2]  + u0.w * ys[a][3]
                + u1.x * ys[a][4]  + u1.y * ys[a][5]  + u1.z * ys[a][6]  + u1.w * ys[a][7]
                + u2.x * ys[a][8]  + u2.y * ys[a][9]  + u2.z * ys[a][10] + u2.w * ys[a][11]
                + u3.x * ys[a][12] + u3.y * ys[a][13] + u3.z * ys[a][14] + u3.w * ys[a][15];
        __stcs(&out_mu[((size_t)e * Aa + a) * Tt + i], s);
    }

    // cov[i][j] = kssd[|i-j|] - dot16(U[i], Ks[j]); written 8x streaming
    const int lane = tid & 31;
    const int grp  = tid >> 5;
    const int j0   = lane * 4;
    float4 s16[16];                                   // full St[:, j0..j0+3] cache
    #pragma unroll
    for (int n = 0; n < 16; n++) s16[n] = *(const float4*)&St[n][j0];

    for (int step = 0; step < Tt / 8; step++) {
        int i = step * 8 + grp;
        float4 u0 = *(const float4*)&U[i][0];          // broadcast LDS.128 x4
        float4 u1 = *(const float4*)&U[i][4];
        float4 u2 = *(const float4*)&U[i][8];
        float4 u3 = *(const float4*)&U[i][12];

        float a0 = u0.x * s16[0].x + u0.y * s16[1].x + u0.z * s16[2].x + u0.w * s16[3].x
                 + u1.x * s16[4].x + u1.y * s16[5].x + u1.z * s16[6].x + u1.w * s16[7].x
                 + u2.x * s16[8].x + u2.y * s16[9].x + u2.z * s16[10].x + u2.w * s16[11].x
                 + u3.x * s16[12].x + u3.y * s16[13].x + u3.z * s16[14].x + u3.w * s16[15].x;
        float a1 = u0.x * s16[0].y + u0.y * s16[1].y + u0.z * s16[2].y + u0.w * s16[3].y
                 + u1.x * s16[4].y + u1.y * s16[5].y + u1.z * s16[6].y + u1.w * s16[7].y
                 + u2.x * s16[8].y + u2.y * s16[9].y + u2.z * s16[10].y + u2.w * s16[11].y
                 + u3.x * s16[12].y + u3.y * s16[13].y + u3.z * s16[14].y + u3.w * s16[15].y;
        float a2 = u0.x * s16[0].z + u0.y * s16[1].z + u0.z * s16[2].z + u0.w * s16[3].z
                 + u1.x * s16[4].z + u1.y * s16[5].z + u1.z * s16[6].z + u1.w * s16[7].z
                 + u2.x * s16[8].z + u2.y * s16[9].z + u2.z * s16[10].z + u2.w * s16[11].z
                 + u3.x * s16[12].z + u3.y * s16[13].z + u3.z * s16[14].z + u3.w * s16[15].z;
        float a3 = u0.x * s16[0].w + u0.y * s16[1].w + u0.z * s16[2].w + u0.w * s16[3].w
                 + u1.x * s16[4].w + u1.y * s16[5].w + u1.z * s16[6].w + u1.w * s16[7].w
                 + u2.x * s16[8].w + u2.y * s16[9].w + u2.z * s16[10].w + u2.w * s16[11].w
                 + u3.x * s16[12].w + u3.y * s16[13].w + u3.z * s16[14].w + u3.w * s16[15].w;

        int d0 = i - j0;       d0 = d0 < 0 ? -d0 : d0;
        int d1 = i - (j0 + 1); d1 = d1 < 0 ? -d1 : d1;
        int d2 = i - (j0 + 2); d2 = d2 < 0 ? -d2 : d2;
        int d3 = i - (j0 + 3); d3 = d3 < 0 ? -d3 : d3;
        float4 v;
        v.x = kssd[d0] - a0;
        v.y = kssd[d1] - a1;
        v.z = kssd[d2] - a2;
        v.w = kssd[d3] - a3;
        size_t base = (((size_t)e * Aa) * Tt + i) * Tt + j0;
        #pragma unroll
        for (int a = 0; a < Aa; a++) {
            __stcs((float4*)&out_cov[base + (size_t)a * Tt * Tt], v);  // streaming STG.128
        }
    }
}

// ---------------------------------------------------------------------------
extern "C" void kernel_launch(void* const* d_in, const int* in_sizes, int n_in,
                              void* d_out, int out_size)
{
    const float* x  = (const float*)d_in[0];
    // d_in[1] = a, d_in[2] = da (unused by reference)
    const float* W1 = (const float*)d_in[3];
    const float* b1 = (const float*)d_in[4];
    const float* W2 = (const float*)d_in[5];
    const float* b2 = (const float*)d_in[6];
    const float* Wt = (const float*)d_in[7];
    const float* bt = (const float*)d_in[8];
    const float* Wa = (const float*)d_in[9];
    const float* ba = (const float*)d_in[10];
    const float* tq = (const float*)d_in[11];

    float* out     = (float*)d_out;
    float* out_mu  = out;                                   // E*A*T floats
    float* out_cov = out + (size_t)E_TOT * Aa * Tt;         // E*A*T*T floats

    float* h2 = nullptr; float* hd = nullptr;
    cudaGetSymbolAddress((void**)&h2, g_h2);
    cudaGetSymbolAddress((void**)&hd, g_head);

    // fused layer1+layer2: [512,256] -> 256 blocks (no h1 round-trip)
    fused_l12_kernel<<<dim3(E_TOT / 16, Hh / 32), 256>>>(x, W1, b1, W2, b2);
    // heads: [512,144] = h2 @ [Wt;Wa]^T + [bt;ba], k=256 -> 288 blocks
    heads_kernel<<<dim3(E_TOT / 16, HO / 16), 256>>>(h2, Wt, Wa, bt, ba, hd);

    gp_kernel<<<E_TOT, 256>>>(tq, out_mu, out_cov);
}

// round 17
// speedup vs baseline: 1.1502x; 1.1502x over previous
#include <cuda_runtime.h>
#include <cuda_bf16.h>
#include <cstddef>

#define E_TOT 512
#define Dd    64
#define Hh    256
#define Nn    16
#define Aa    8
#define Tt    128
#define HO    (Nn + Aa * Nn)   // 144 head outputs
#define USTR  20               // U row stride: 80B = 5x16B, float4-aligned

#define SF2   0.01f
#define SN2   0.01f
#define NEG_HALF_INV_L2 (-50.0f)   // -0.5 / 0.1^2

// scratch (no allocation allowed -> device globals)
__device__ float g_h1[E_TOT * Hh];     // layer-1 activations
__device__ float g_h2[E_TOT * Hh];     // layer-2 activations
__device__ float g_head[E_TOT * HO];   // [times(16) | anchors(128)] per e

// ---------------------------------------------------------------------------
// Tiled GEMM (R15 body) + PDL: W-tile prefetch (independent) happens BEFORE
// cudaGridDependencySynchronize(); the dependent A prefetch after. Trigger
// fires after this kernel's stores so the successor can overlap its prologue.
// ---------------------------------------------------------------------------
template<int BN, int KTOT, bool DOTANH, bool SPLITW, bool PDL>
__global__ __launch_bounds__(256)
void gemm_kernel(const float* __restrict__ A,
                 const float* __restrict__ W,    // or Wt when SPLITW
                 const float* __restrict__ Wb,   // Wa when SPLITW
                 const float* __restrict__ bias,    // or bt
                 const float* __restrict__ biasb,   // ba when SPLITW
                 float* __restrict__ C, int OUTC)
{
    constexpr int BM  = 16;
    constexpr int RPT = (BM * BN) / 256;    // rows per thread: 2 (BN=32), 1 (BN=16)
    constexpr int NA  = (BM * 16) / 256;    // A float4s per thread (1)
    constexpr int NW  = (BN * 16) / 256;    // W float4s per thread (2 or 1)
    __shared__ __align__(16) float Ash[BM][68];
    __shared__ __align__(16) float Bsh[BN][68];

    const int tid  = threadIdx.x;
    const int c    = tid % BN;
    const int rg   = tid / BN;
    const int row0 = blockIdx.x * BM;
    const int col0 = blockIdx.y * BN;

    float acc[RPT][4];
    #pragma unroll
    for (int r = 0; r < RPT; r++)
        #pragma unroll
        for (int q = 0; q < 4; q++) acc[r][q] = 0.0f;

    float4 pa[NA], pw[NW];
    // prefetch W tile 0 -- independent of the predecessor kernel's output
    #pragma unroll
    for (int u = 0; u < NW; u++) {
        int i = tid + u * 256;
        int cc = i >> 4, kq = (i & 15) << 2;
        int cg = col0 + cc;
        const float* src;
        if (SPLITW) src = (cg < Nn) ? &W[cg * KTOT + kq]
                                    : &Wb[(cg - Nn) * KTOT + kq];
        else        src = &W[cg * KTOT + kq];
        pw[u] = *(const float4*)src;
    }
    if (PDL) cudaGridDependencySynchronize();
    // prefetch A tile 0 -- dependent data
    #pragma unroll
    for (int u = 0; u < NA; u++) {
        int i = tid + u * 256;
        int r = i >> 4, kq = (i & 15) << 2;
        pa[u] = *(const float4*)&A[(row0 + r) * KTOT + kq];
    }

    for (int k0 = 0; k0 < KTOT; k0 += 64) {
        // commit prefetched tile to smem
        #pragma unroll
        for (int u = 0; u < NA; u++) {
            int i = tid + u * 256;
            int r = i >> 4, kq = (i & 15) << 2;
            *(float4*)&Ash[r][kq] = pa[u];
        }
        #pragma unroll
        for (int u = 0; u < NW; u++) {
            int i = tid + u * 256;
            int cc = i >> 4, kq = (i & 15) << 2;
            *(float4*)&Bsh[cc][kq] = pw[u];
        }
        __syncthreads();

        // prefetch next tile (LDG latency overlaps the inner loop)
        if (k0 + 64 < KTOT) {
            int kn = k0 + 64;
            #pragma unroll
            for (int u = 0; u < NA; u++) {
                int i = tid + u * 256;
                int r = i >> 4, kq = (i & 15) << 2;
                pa[u] = *(const float4*)&A[(row0 + r) * KTOT + kn + kq];
            }
            #pragma unroll
            for (int u = 0; u < NW; u++) {
                int i = tid + u * 256;
                int cc = i >> 4, kq = (i & 15) << 2;
                int cg = col0 + cc;
                const float* src;
                if (SPLITW) src = (cg < Nn) ? &W[cg * KTOT + kn + kq]
                                            : &Wb[(cg - Nn) * KTOT + kn + kq];
                else        src = &W[cg * KTOT + kn + kq];
                pw[u] = *(const float4*)src;
            }
        }

        #pragma unroll
        for (int kk = 0; kk < 64; kk += 4) {
            float4 b4 = *(const float4*)&Bsh[c][kk];       // LDS.128, dedup'd
            #pragma unroll
            for (int r = 0; r < RPT; r++) {
                float4 a4 = *(const float4*)&Ash[rg * RPT + r][kk];  // broadcast
                acc[r][0] += a4.x * b4.x;
                acc[r][1] += a4.y * b4.y;
                acc[r][2] += a4.z * b4.z;
                acc[r][3] += a4.w * b4.w;
            }
        }
        __syncthreads();
    }

    #pragma unroll
    for (int r = 0; r < RPT; r++) {
        int row = row0 + rg * RPT + r;
        int col = col0 + c;
        float bv;
        if (SPLITW) bv = (col < Nn) ? bias[col] : biasb[col - Nn];
        else        bv = bias[col];
        float v = (acc[r][0] + acc[r][1]) + (acc[r][2] + acc[r][3]) + bv;
        if (DOTANH) v = tanhf(v);
        C[row * OUTC + col] = v;
    }
    cudaTriggerProgrammaticLaunchCompletion();   // successor may start
}

// ---------------------------------------------------------------------------
// GP per environment e. 512 blocks, 256 threads. (R15 body; PDL preamble:
// tq load + kssd table computed BEFORE the dependency sync, g_head after.)
// ---------------------------------------------------------------------------
__global__ __launch_bounds__(256)
void gp_kernel(const float* __restrict__ tq_g,
               float* __restrict__ out_mu,
               float* __restrict__ out_cov)
{
    __shared__ float tq[Tt];
    __shared__ float kssd[Tt];                        // Kss[i][j] == kssd[|i-j|]
    __shared__ float tt[Nn];
    __shared__ float ys[Aa][Nn];
    __shared__ float Aug[Nn][2 * Nn + 1];             // [K | I] -> [I | K^-1]
    __shared__ float colk[Nn];
    __shared__ __align__(16) float St[Nn][Tt + 4];    // Ks^T, pad 132 (16B mult)
    __shared__ __align__(16) float U[Tt][USTR];       // U = Ks K^-1, stride 20

    const int e   = blockIdx.x;
    const int tid = threadIdx.x;

    // -- independent prologue: tq + kssd (no g_head dependence) --
    if (tid < Tt) tq[tid] = tq_g[tid];
    __syncthreads();
    if (tid < Tt) {
        float d = tq[tid] - tq[0];
        kssd[tid] = SF2 * __expf(NEG_HALF_INV_L2 * d * d);
    }

    cudaGridDependencySynchronize();                  // wait for heads output

    if (tid < Nn) tt[tid] = g_head[e * HO + tid];
    if (tid >= 128 && tid < 128 + Aa * Nn) {
        int q = tid - 128;
        ys[q >> 4][q & 15] = g_head[e * HO + Nn + q];
    }
    __syncthreads();

    // build [K + sn2 I | I]
    {
        int i = tid >> 4, j = tid & 15;
        float d = tt[i] - tt[j];
        float v = SF2 * __expf(NEG_HALF_INV_L2 * d * d);
        if (i == j) v += SN2;
        Aug[i][j] = v;
        Aug[i][Nn + j] = (i == j) ? 1.0f : 0.0f;
    }
    __syncthreads();

    // Gauss-Jordan (SPD, no pivoting needed, cond(K) <= 17)
    for (int k = 0; k < Nn; k++) {
        float pinv = 1.0f / Aug[k][k];
        __syncthreads();
        if (tid < 32) Aug[k][tid] *= pinv;
        if (tid >= 32 && tid < 48) colk[tid - 32] = Aug[tid - 32][k];
        __syncthreads();
        {
            int idx = tid;
            int i0 = idx >> 5, j0 = idx & 31;
            if (i0 != k) Aug[i0][j0] -= colk[i0] * Aug[k][j0];
            idx += 256;
            int i1 = idx >> 5, j1 = idx & 31;
            if (i1 != k) Aug[i1][j1] -= colk[i1] * Aug[k][j1];
        }
        __syncthreads();
    }

    // Ks transposed: St[n][j] = sf2 * exp(-0.5 (tq[j]-t[n])^2 / l2)
    for (int idx = tid; idx < Tt * Nn; idx += 256) {
        int j = idx >> 4, n = idx & 15;
        float d = tq[j] - tt[n];
        St[n][j] = SF2 * __expf(NEG_HALF_INV_L2 * d * d);
    }
    __syncthreads();

    // U[i][n] = sum_m Ks[i][m] * Kinv[m][n]
    for (int idx = tid; idx < Tt * Nn; idx += 256) {
        int i = idx >> 4, n = idx & 15;
        float s = 0.0f;
        #pragma unroll
        for (int m = 0; m < Nn; m++) s += St[m][i] * Aug[m][Nn + n];
        U[i][n] = s;
    }
    __syncthreads();

    // mu[a][i] = dot16(U[i], y[a])   (U rows are 4 aligned float4s)
    for (int idx = tid; idx < Aa * Tt; idx += 256) {
        int a = idx >> 7, i = idx & 127;
        float4 u0 = *(const float4*)&U[i][0];
        float4 u1 = *(const float4*)&U[i][4];
        float4 u2 = *(const float4*)&U[i][8];
        float4 u3 = *(const float4*)&U[i][12];
        float s = u0.x * ys[a][0]  + u0.y * ys[a][1]  + u0.z * ys[a][2]  + u0.w * ys[a][3]
                + u1.x * ys[a][4]  + u1.y * ys[a][5]  + u1.z * ys[a][6]  + u1.w * ys[a][7]
                + u2.x * ys[a][8]  + u2.y * ys[a][9]  + u2.z * ys[a][10] + u2.w * ys[a][11]
                + u3.x * ys[a][12] + u3.y * ys[a][13] + u3.z * ys[a][14] + u3.w * ys[a][15];
        __stcs(&out_mu[((size_t)e * Aa + a) * Tt + i], s);
    }

    // cov[i][j] = kssd[|i-j|] - dot16(U[i], Ks[j]); written 8x streaming
    const int lane = tid & 31;
    const int grp  = tid >> 5;
    const int j0   = lane * 4;
    float4 s16[16];                                   // full St[:, j0..j0+3] cache
    #pragma unroll
    for (int n = 0; n < 16; n++) s16[n] = *(const float4*)&St[n][j0];

    for (int step = 0; step < Tt / 8; step++) {
        int i = step * 8 + grp;
        float4 u0 = *(const float4*)&U[i][0];          // broadcast LDS.128 x4
        float4 u1 = *(const float4*)&U[i][4];
        float4 u2 = *(const float4*)&U[i][8];
        float4 u3 = *(const float4*)&U[i][12];

        float a0 = u0.x * s16[0].x + u0.y * s16[1].x + u0.z * s16[2].x + u0.w * s16[3].x
                 + u1.x * s16[4].x + u1.y * s16[5].x + u1.z * s16[6].x + u1.w * s16[7].x
                 + u2.x * s16[8].x + u2.y * s16[9].x + u2.z * s16[10].x + u2.w * s16[11].x
                 + u3.x * s16[12].x + u3.y * s16[13].x + u3.z * s16[14].x + u3.w * s16[15].x;
        float a1 = u0.x * s16[0].y + u0.y * s16[1].y + u0.z * s16[2].y + u0.w * s16[3].y
                 + u1.x * s16[4].y + u1.y * s16[5].y + u1.z * s16[6].y + u1.w * s16[7].y
                 + u2.x * s16[8].y + u2.y * s16[9].y + u2.z * s16[10].y + u2.w * s16[11].y
                 + u3.x * s16[12].y + u3.y * s16[13].y + u3.z * s16[14].y + u3.w * s16[15].y;
        float a2 = u0.x * s16[0].z + u0.y * s16[1].z + u0.z * s16[2].z + u0.w * s16[3].z
                 + u1.x * s16[4].z + u1.y * s16[5].z + u1.z * s16[6].z + u1.w * s16[7].z
                 + u2.x * s16[8].z + u2.y * s16[9].z + u2.z * s16[10].z + u2.w * s16[11].z
                 + u3.x * s16[12].z + u3.y * s16[13].z + u3.z * s16[14].z + u3.w * s16[15].z;
        float a3 = u0.x * s16[0].w + u0.y * s16[1].w + u0.z * s16[2].w + u0.w * s16[3].w
                 + u1.x * s16[4].w + u1.y * s16[5].w + u1.z * s16[6].w + u1.w * s16[7].w
                 + u2.x * s16[8].w + u2.y * s16[9].w + u2.z * s16[10].w + u2.w * s16[11].w
                 + u3.x * s16[12].w + u3.y * s16[13].w + u3.z * s16[14].w + u3.w * s16[15].w;

        int d0 = i - j0;       d0 = d0 < 0 ? -d0 : d0;
        int d1 = i - (j0 + 1); d1 = d1 < 0 ? -d1 : d1;
        int d2 = i - (j0 + 2); d2 = d2 < 0 ? -d2 : d2;
        int d3 = i - (j0 + 3); d3 = d3 < 0 ? -d3 : d3;
        float4 v;
        v.x = kssd[d0] - a0;
        v.y = kssd[d1] - a1;
        v.z = kssd[d2] - a2;
        v.w = kssd[d3] - a3;
        size_t base = (((size_t)e * Aa) * Tt + i) * Tt + j0;
        #pragma unroll
        for (int a = 0; a < Aa; a++) {
            __stcs((float4*)&out_cov[base + (size_t)a * Tt * Tt], v);  // streaming STG.128
        }
    }
}

// ---------------------------------------------------------------------------
extern "C" void kernel_launch(void* const* d_in, const int* in_sizes, int n_in,
                              void* d_out, int out_size)
{
    const float* x  = (const float*)d_in[0];
    // d_in[1] = a, d_in[2] = da (unused by reference)
    const float* W1 = (const float*)d_in[3];
    const float* b1 = (const float*)d_in[4];
    const float* W2 = (const float*)d_in[5];
    const float* b2 = (const float*)d_in[6];
    const float* Wt = (const float*)d_in[7];
    const float* bt = (const float*)d_in[8];
    const float* Wa = (const float*)d_in[9];
    const float* ba = (const float*)d_in[10];
    const float* tq = (const float*)d_in[11];

    float* out     = (float*)d_out;
    float* out_mu  = out;                                   // E*A*T floats
    float* out_cov = out + (size_t)E_TOT * Aa * Tt;         // E*A*T*T floats

    float* h1 = nullptr; float* h2 = nullptr; float* hd = nullptr;
    cudaGetSymbolAddress((void**)&h1, g_h1);
    cudaGetSymbolAddress((void**)&h2, g_h2);
    cudaGetSymbolAddress((void**)&hd, g_head);

    cudaLaunchAttribute pdlAttr;
    pdlAttr.id = cudaLaunchAttributeProgrammaticStreamSerialization;
    pdlAttr.val.programmaticStreamSerializationAllowed = 1;

    // layer 1: no predecessor -> plain launch
    gemm_kernel<32, Dd, true, false, false>
        <<<dim3(E_TOT / 16, Hh / 32), 256>>>(x, W1, nullptr, b1, nullptr, h1, Hh);

    // layer 2: PDL overlap with layer 1 tail
    {
        cudaLaunchConfig_t cfg = {};
        cfg.gridDim  = dim3(E_TOT / 16, Hh / 32);
        cfg.blockDim = dim3(256);
        cfg.attrs    = &pdlAttr;
        cfg.numAttrs = 1;
        cudaLaunchKernelEx(&cfg, gemm_kernel<32, Hh, true, false, true>,
                           (const float*)h1, W2, (const float*)nullptr,
                           b2, (const float*)nullptr, h2, (int)Hh);
    }
    // heads: PDL overlap with layer 2 tail
    {
        cudaLaunchConfig_t cfg = {};
        cfg.gridDim  = dim3(E_TOT / 16, HO / 16);
        cfg.blockDim = dim3(256);
        cfg.attrs    = &pdlAttr;
        cfg.numAttrs = 1;
        cudaLaunchKernelEx(&cfg, gemm_kernel<16, Hh, false, true, true>,
                           (const float*)h2, Wt, Wa, bt, ba, hd, (int)HO);
    }
    // gp: PDL overlap (tq + kssd prologue) with heads tail
    {
        cudaLaunchConfig_t cfg = {};
        cfg.gridDim  = dim3(E_TOT);
        cfg.blockDim = dim3(256);
        cfg.attrs    = &pdlAttr;
        cfg.numAttrs = 1;
        cudaLaunchKernelEx(&cfg, gp_kernel, tq, out_mu, out_cov);
    }
}